// round 17
// baseline (speedup 1.0000x reference)
#include <cuda_runtime.h>

// SSD post-processing: decode + per-class greedy NMS.
//   loc_data  [8, 3000, 4]  f32
//   conf_data [8, 3000, 21] f32
//   priors    [3000, 4]     f32
//   out       [8, 21, 200, 5] f32  (score, x1, y1, x2, y2), zero-padded
//
// One CTA per (class, batch), grid (21, 8), 256 threads.
// R16 kernel (176.5us) with ONE structural change: the serial accept loop
// (per-accept: LDS+ballot+shfl+LDS+IoU+ballot+STS+__syncthreads, ~300 cyc and
// ~200 block barriers/CTA) is replaced by a suppression-bitmask sweep:
//   - after Phase A, each alive thread computes kill bits vs alive tile
//     candidates j > tid (iterating set bits of the published alive words)
//     and publishes a 256-bit killmask to smem;
//   - greedy resolution = uniform redundant register sweep on all threads:
//     i = ffs(alive); owner writes; alive &= ~killm[i]; clear bit; cnt++.
//     ~45 cyc/accept, ZERO per-accept barriers (3 per tile).
// Same IoU values applied in the same order => bit-identical output.

#define NP    3000
#define NPAD  4096
#define NC    21
#define TOPK  200
#define NT    256
#define NWARP (NT / 32)
#define EPT   (NPAD / NT)                 // 16 keys per thread
#define SW(i) ((i) ^ (((i) >> 4) & 15))   // bank swizzle for u64 keys[]

typedef unsigned long long ull;

__device__ __forceinline__ void cexch(ull& a, ull& b, bool desc) {
    if (desc ? (a < b) : (a > b)) { ull t = a; a = b; b = t; }
}

// reference-exact IoU (no FMA contraction)
__device__ __forceinline__ float iou_rn(float ax1, float ay1, float ax2, float ay2, float aa,
                                        float bx1, float by1, float bx2, float by2, float ba)
{
    float ltx = fmaxf(ax1, bx1);
    float lty = fmaxf(ay1, by1);
    float rbx = fminf(ax2, bx2);
    float rby = fminf(ay2, by2);
    float wx  = fmaxf(__fsub_rn(rbx, ltx), 0.0f);
    float wy  = fmaxf(__fsub_rn(rby, lty), 0.0f);
    float inter = __fmul_rn(wx, wy);
    float uni   = __fsub_rn(__fadd_rn(aa, ba), inter);
    return __fdiv_rn(inter, fmaxf(uni, 1e-12f));
}

__global__ __launch_bounds__(NT, 2) void ssd_post_kernel(
    const float* __restrict__ loc,
    const float* __restrict__ conf,
    const float* __restrict__ priors,
    float* __restrict__ out)
{
    __shared__ ull      keys[NPAD];      // 32 KB
    __shared__ float4   sbox[NT];        // tile candidate boxes
    __shared__ float    sare[NT];        // tile candidate areas
    __shared__ float4   abox[TOPK];      // accepted boxes
    __shared__ float    aare[TOPK];      // accepted areas
    __shared__ unsigned salv[NWARP];     // per-warp alive ballots
    __shared__ unsigned killm[NT * 8];   // per-candidate 256-bit killmasks (8 KB)
    __shared__ int      s_nvalid;

    const int c    = blockIdx.x;
    const int b    = blockIdx.y;
    const int tid  = threadIdx.x;
    const int lane = tid & 31;
    const int wix  = tid >> 5;

    float* outp = out + (size_t)(b * NC + c) * (TOPK * 5);
    for (int k = tid; k < TOPK * 5; k += NT) outp[k] = 0.0f;
    if (c == 0) return;  // background class: zeros only

    if (tid == 0) s_nvalid = 0;
    __syncthreads();

    // ---- build sort keys: (sortable(score) << 32) | ~idx  (stable desc) ----
    const float* confb = conf + (size_t)b * NP * NC + c;
    int myValid = 0;
    #pragma unroll
    for (int w = 0; w < EPT; ++w) {
        int p = tid + w * NT;
        ull key = 0ULL;                               // padding: below everything
        if (p < NP) {
            float s = confb[(size_t)p * NC];
            bool v = (s > 0.01f);
            myValid += v ? 1 : 0;
            if (!v) s = __int_as_float(0xff800000);   // -inf: sorts after valid
            unsigned u = __float_as_uint(s);
            u = (u & 0x80000000u) ? ~u : (u | 0x80000000u);
            key = ((ull)u << 32) | (unsigned)(~p);
        }
        keys[SW(p)] = key;
    }
    #pragma unroll
    for (int o = 16; o > 0; o >>= 1)
        myValid += __shfl_down_sync(0xffffffffu, myValid, o);
    if (lane == 0 && myValid) atomicAdd(&s_nvalid, myValid);
    __syncthreads();

    // ---- bitonic sort, descending (register-fused) ----
    // fused register-local stages k = 2..16 (all strides < 16)
    {
        const int base = tid * EPT;
        ull r[EPT];
        #pragma unroll
        for (int m = 0; m < EPT; ++m) r[m] = keys[SW(base + m)];
        #pragma unroll
        for (int k = 2; k <= 16; k <<= 1) {
            #pragma unroll
            for (int j = k >> 1; j >= 1; j >>= 1) {
                #pragma unroll
                for (int m = 0; m < EPT; ++m)
                    if (!(m & j))
                        cexch(r[m], r[m | j], ((base + m) & k) == 0);
            }
        }
        #pragma unroll
        for (int m = 0; m < EPT; ++m) keys[SW(base + m)] = r[m];
    }
    __syncthreads();

    for (int k = 32; k <= NPAD; k <<= 1) {
        // smem substages: strides >= 16, pair-expanded (all threads active)
        for (int j = k >> 1; j >= 16; j >>= 1) {
            #pragma unroll
            for (int w = 0; w < NPAD / (2 * NT); ++w) {
                int p   = tid + w * NT;
                int i   = ((p & ~(j - 1)) << 1) | (p & (j - 1));
                int ixj = i | j;
                ull a  = keys[SW(i)];
                ull bb = keys[SW(ixj)];
                if (((i & k) == 0) ? (a < bb) : (a > bb)) {
                    keys[SW(i)] = bb; keys[SW(ixj)] = a;
                }
            }
            __syncthreads();
        }
        // register-local tail: strides 8,4,2,1 (uniform direction per thread)
        {
            const int  base = tid * EPT;
            const bool desc = ((base & k) == 0);
            ull r[EPT];
            #pragma unroll
            for (int m = 0; m < EPT; ++m) r[m] = keys[SW(base + m)];
            #pragma unroll
            for (int j = 8; j >= 1; j >>= 1) {
                #pragma unroll
                for (int m = 0; m < EPT; ++m)
                    if (!(m & j)) cexch(r[m], r[m | j], desc);
            }
            #pragma unroll
            for (int m = 0; m < EPT; ++m) keys[SW(base + m)] = r[m];
        }
        __syncthreads();
    }

    // ---- tiled candidate-driven NMS ----
    const int nvalid = s_nvalid;   // valid candidates form the sorted prefix
    const float* locb = loc + (size_t)b * NP * 4;

    int cnt = 0;                   // uniform register across all threads

    for (int tb = 0; tb < nvalid && cnt < TOPK; tb += NT) {
        const int j = tb + tid;
        ull key = keys[SW(j)];
        bool myAlive = (j < nvalid) && ((key >> 63) != 0ULL);

        // decode my candidate (exact reference op order) into regs + tile smem
        float mx1 = 0.f, my1 = 0.f, mx2 = 0.f, my2 = 0.f, mar = 0.f, ms = 0.f;
        if (myAlive) {
            int idx = (int)(~(unsigned)key);
            ms = __uint_as_float((unsigned)(key >> 32) & 0x7FFFFFFFu);
            float4 l  = *(const float4*)(locb + (size_t)idx * 4);
            float4 pr = *(const float4*)(priors + (size_t)idx * 4);
            float cx = __fadd_rn(pr.x, __fmul_rn(__fmul_rn(l.x, 0.1f), pr.z));
            float cy = __fadd_rn(pr.y, __fmul_rn(__fmul_rn(l.y, 0.1f), pr.w));
            float w  = __fmul_rn(pr.z, expf(__fmul_rn(l.z, 0.2f)));
            float hh = __fmul_rn(pr.w, expf(__fmul_rn(l.w, 0.2f)));
            mx1 = __fsub_rn(cx, __fmul_rn(0.5f, w));
            my1 = __fsub_rn(cy, __fmul_rn(0.5f, hh));
            mx2 = __fadd_rn(mx1, w);
            my2 = __fadd_rn(my1, hh);
            mar = __fmul_rn(__fsub_rn(mx2, mx1), __fsub_rn(my2, my1));
            sbox[tid] = make_float4(mx1, my1, mx2, my2);
            sare[tid] = mar;
        }

        // Phase A: branchless pipelined test vs accepted list; warp-vote
        // early-out every 16 boxes (dead lanes vote 'suppressed')
        {
            bool ov = !myAlive;
            int q = 0;
            while (q < cnt) {
                int qe = (q + 16 < cnt) ? (q + 16) : cnt;   // uniform
                #pragma unroll 4
                for (; q < qe; ++q) {
                    float4 ab = abox[q];
                    float ii = iou_rn(mx1, my1, mx2, my2, mar,
                                      ab.x, ab.y, ab.z, ab.w, aare[q]);
                    ov |= (ii > 0.45f);
                }
                if (__all_sync(0xffffffffu, ov)) break;   // whole warp settled
            }
            myAlive = myAlive && !ov;
        }
        unsigned wm = __ballot_sync(0xffffffffu, myAlive);
        if (lane == 0) salv[wix] = wm;
        __syncthreads();   // publish sbox/sare/salv

        // Killmask: alive thread tid computes bits of alive j > tid it would
        // suppress (iterating only set bits => cost ~ survivors)
        {
            unsigned kill[8] = {0, 0, 0, 0, 0, 0, 0, 0};
            if (myAlive) {
                #pragma unroll 1
                for (int w = wix; w < NWARP; ++w) {
                    unsigned m = salv[w];
                    if (w == wix) m &= ~((2u << lane) - 1u);  // bits strictly > lane
                    while (m) {
                        int jj = (w << 5) + __ffs(m) - 1;
                        m &= m - 1u;
                        float4 ob = sbox[jj];
                        float ii = iou_rn(ob.x, ob.y, ob.z, ob.w, sare[jj],
                                          mx1, my1, mx2, my2, mar);
                        if (ii > 0.45f) kill[w] |= 1u << (jj & 31);
                    }
                }
            }
            // publish my killmask row (dead rows stale but never applied)
            uint4* kp = (uint4*)&killm[tid * 8];
            kp[0] = make_uint4(kill[0], kill[1], kill[2], kill[3]);
            kp[1] = make_uint4(kill[4], kill[5], kill[6], kill[7]);
        }
        __syncthreads();   // publish killm

        // Sweep: uniform redundant greedy resolution, barrier-free
        {
            unsigned alive[8];
            #pragma unroll
            for (int w = 0; w < NWARP; ++w) alive[w] = salv[w];

            while (cnt < TOPK) {
                int w0 = -1;
                #pragma unroll
                for (int w = NWARP - 1; w >= 0; --w)
                    if (alive[w]) w0 = w;             // lowest nonzero word
                if (w0 < 0) break;                    // tile exhausted (uniform)
                unsigned aw = alive[0];
                #pragma unroll
                for (int w = 1; w < NWARP; ++w)
                    if (w == w0) aw = alive[w];
                int i = (w0 << 5) + __ffs(aw) - 1;    // first alive candidate

                if (tid == i) {
                    abox[cnt] = make_float4(mx1, my1, mx2, my2);
                    aare[cnt] = mar;
                    float* o = outp + cnt * 5;
                    o[0] = ms; o[1] = mx1; o[2] = my1; o[3] = mx2; o[4] = my2;
                }
                // apply candidate i's killmask (broadcast LDS) + clear bit i
                const uint4* kp = (const uint4*)&killm[i * 8];
                uint4 k0 = kp[0], k1 = kp[1];
                alive[0] &= ~k0.x; alive[1] &= ~k0.y;
                alive[2] &= ~k0.z; alive[3] &= ~k0.w;
                alive[4] &= ~k1.x; alive[5] &= ~k1.y;
                alive[6] &= ~k1.z; alive[7] &= ~k1.w;
                #pragma unroll
                for (int w = 0; w < NWARP; ++w)
                    if (w == w0) alive[w] &= ~(1u << (i & 31));
                cnt++;                                // uniform
            }
        }
        __syncthreads();   // publish abox/aare; safe to overwrite sbox/salv
    }
}

extern "C" void kernel_launch(void* const* d_in, const int* in_sizes, int n_in,
                              void* d_out, int out_size)
{
    const float* loc = nullptr;
    const float* conf = nullptr;
    const float* priors = nullptr;
    for (int i = 0; i < n_in; i++) {
        if (in_sizes[i] == 8 * NP * 4)       loc    = (const float*)d_in[i];
        else if (in_sizes[i] == 8 * NP * NC) conf   = (const float*)d_in[i];
        else if (in_sizes[i] == NP * 4)      priors = (const float*)d_in[i];
    }
    float* out = (float*)d_out;

    dim3 grid(NC, 8);
    ssd_post_kernel<<<grid, NT>>>(loc, conf, priors, out);
}